// round 5
// baseline (speedup 1.0000x reference)
#include <cuda_runtime.h>
#include <cuda_bf16.h>
#include <cstdint>

#define BATCH 512
#define SEQ   1024
#define NT    64
#define NSB   (BATCH * SEQ)

// ---------------- device scratch (no allocs allowed) ----------------
__device__ float g_expT[NT * NT];   // exp(transitions)
__device__ float g_expEnd[NT];      // exp(end_transitions)
__device__ float g_logz[BATCH];
__device__ float g_score[BATCH];
__device__ unsigned long long g_mask_ptr;   // resolved raw mask pointer
__device__ unsigned long long g_tags_ptr;   // resolved raw tags pointer
__device__ int   g_mask8;                   // 1 if mask is 1 byte/elem, 0 if int32
__device__ int   g_tags64;                  // 1 if tags are int64, 0 if int32
__device__ unsigned char g_maskb[NSB];      // canonical mask (1 byte/elem)
__device__ int           g_tagsi[NSB];      // canonical tags (int32)

// ---------------- small PTX helpers ----------------
__device__ __forceinline__ float ex2f(float x) {
    float r; asm("ex2.approx.ftz.f32 %0, %1;" : "=f"(r) : "f"(x)); return r;
}
__device__ __forceinline__ float lg2f(float x) {
    float r; asm("lg2.approx.ftz.f32 %0, %1;" : "=f"(r) : "f"(x)); return r;
}
__device__ __forceinline__ unsigned long long pack2(float x, float y) {
    unsigned long long r; asm("mov.b64 %0, {%1, %2};" : "=l"(r) : "f"(x), "f"(y)); return r;
}
__device__ __forceinline__ void unpack2(unsigned long long v, float& x, float& y) {
    asm("mov.b64 {%0, %1}, %2;" : "=f"(x), "=f"(y) : "l"(v));
}
__device__ __forceinline__ unsigned long long ffma2(unsigned long long a, unsigned long long b, unsigned long long c) {
    unsigned long long d; asm("fma.rn.f32x2 %0, %1, %2, %3;" : "=l"(d) : "l"(a), "l"(b), "l"(c)); return d;
}
__device__ __forceinline__ unsigned long long fadd2(unsigned long long a, unsigned long long b) {
    unsigned long long d; asm("add.rn.f32x2 %0, %1, %2;" : "=l"(d) : "l"(a), "l"(b)); return d;
}

// ---------------- content + width sniff ----------------
// Mask buffer: every byte is 0/1 -> (word & 0xFEFEFEFE)==0 for all words.
// Tags buffer (random 0..63): fails that test with overwhelming probability.
// Mask width: int32 mask words are 0/1; byte mask (any true) has a word > 1.
// Tags width: int64 <=> all odd 32-bit words are zero (values < 64).
__global__ void crf_sniff_kernel(const unsigned int* __restrict__ a,
                                 const unsigned int* __restrict__ b) {
    int am = 1, bm = 1;
    for (int i = 0; i < 64; ++i) {
        am &= ((a[i] & 0xFEFEFEFEu) == 0u);
        bm &= ((b[i] & 0xFEFEFEFEu) == 0u);
    }
    const unsigned int* mp = am ? a : b;
    const unsigned int* tp = am ? b : a;
    g_mask_ptr = (unsigned long long)mp;
    g_tags_ptr = (unsigned long long)tp;
    int m8 = 0;
    for (int i = 0; i < 64; ++i) if (mp[i] > 1u) { m8 = 1; break; }
    g_mask8 = m8;
    int t64 = 1;
    for (int i = 1; i < 64; i += 2) t64 &= (tp[i] == 0u);
    g_tags64 = t64;
}

// ---------------- repack mask/tags into canonical layouts ----------------
__global__ void crf_repack_kernel() {
    const int i = blockIdx.x * blockDim.x + threadIdx.x;
    if (i >= NSB) return;
    if (g_mask8) {
        g_maskb[i] = (((const unsigned char*)g_mask_ptr)[i] != 0) ? 1 : 0;
    } else {
        g_maskb[i] = (((const unsigned int*)g_mask_ptr)[i] != 0u) ? 1 : 0;
    }
    if (g_tags64) {
        g_tagsi[i] = (int)((const long long*)g_tags_ptr)[i];
    } else {
        g_tagsi[i] = ((const int*)g_tags_ptr)[i];
    }
}

// ---------------- prep: E = exp(T), expEnd = exp(end) ----------------
__global__ void crf_prep_kernel(const float* __restrict__ trans, const float* __restrict__ endt) {
    int i = blockIdx.x * blockDim.x + threadIdx.x;
    if (i < NT * NT) g_expT[i] = expf(trans[i]);
    if (i < NT)      g_expEnd[i] = expf(endt[i]);
}

// ---------------- forward: one warp per batch ----------------
// Invariant: alpha[j] = ln(v[j]) + c*ln2.  Lane l owns tags l, l+32 (f32x2).
// Normal step:  acc = v @ E;  v' = acc * g,  g = exp2(em*log2e - 6) (prefetched);  c += 6.
// Renorm step (every 8th): also scale by 2^(133-eb(acc[0])); c += eb - 127 (exact).
#define CRF_STEP(T, GX, GY, QM, RBUF, WBUF, REN) do {                            \
    const int   mcur = (QM);                                                     \
    const float gx_c = (GX), gy_c = (GY);                                        \
    { /* prefetch step T+4: load em, fold exp2 off the critical path */          \
        const int tp = (T) + 4;                                                  \
        if (tp < SEQ) {                                                          \
            GX = ex2f(fmaf(emb[tp * NT + l],      L2E, -6.0f));                  \
            GY = ex2f(fmaf(emb[tp * NT + l + 32], L2E, -6.0f));                  \
            QM = (int)mrow[tp];                                                  \
        }                                                                        \
    }                                                                            \
    const ulonglong2* pb = (const ulonglong2*)(pd[RBUF]);                        \
    unsigned long long a0 = 0ull, a1 = 0ull, a2 = 0ull, a3 = 0ull;               \
    _Pragma("unroll")                                                            \
    for (int i = 0; i < 16; ++i) {                                               \
        ulonglong2 q0 = pb[2 * i];                                               \
        ulonglong2 q1 = pb[2 * i + 1];                                           \
        a0 = ffma2(q0.x, E2[4 * i + 0], a0);                                     \
        a1 = ffma2(q0.y, E2[4 * i + 1], a1);                                     \
        a2 = ffma2(q1.x, E2[4 * i + 2], a2);                                     \
        a3 = ffma2(q1.y, E2[4 * i + 3], a3);                                     \
    }                                                                            \
    unsigned long long tot = fadd2(fadd2(a0, a1), fadd2(a2, a3));                \
    float ax, ay; unpack2(tot, ax, ay);                                          \
    if (REN) {                                                                   \
        const float arefn = __shfl_sync(0xffffffffu, ax, 0);                     \
        const int eb = (__float_as_int(arefn) >> 23) & 255;                      \
        if (mcur) {                                                              \
            const float s2 = __int_as_float((260 - eb) << 23);                   \
            vx = ax * gx_c * s2;                                                 \
            vy = ay * gy_c * s2;                                                 \
            c += eb - 127;                                                       \
        }                                                                        \
    } else if (mcur) {                                                           \
        vx = ax * gx_c;                                                          \
        vy = ay * gy_c;                                                          \
        c += 6;                                                                  \
    }                                                                            \
    ((float2*)pd[WBUF])[l]      = make_float2(vx, vx);                           \
    ((float2*)pd[WBUF])[l + 32] = make_float2(vy, vy);                           \
    __syncwarp();                                                                \
} while (0)

__global__ void __launch_bounds__(32, 1) crf_forward_kernel(
    const float* __restrict__ em, const float* __restrict__ startt)
{
    __shared__ __align__(16) float pd[2][2 * NT];  // duplicated-v double buffer
    const int b = blockIdx.x;
    const int l = threadIdx.x;
    const float L2E = 1.4426950408889634f;
    const float LN2 = 0.69314718055994531f;

    unsigned long long E2[NT];
#pragma unroll
    for (int i = 0; i < NT; ++i)
        E2[i] = pack2(g_expT[i * NT + l], g_expT[i * NT + l + 32]);

    const float* emb = em + (size_t)b * SEQ * NT;
    const unsigned char* mrow = g_maskb + (size_t)b * SEQ;

    float vx = ex2f((startt[l] + emb[l]) * L2E);
    float vy = ex2f((startt[l + 32] + emb[l + 32]) * L2E);
    int c = 0;

    ((float2*)pd[0])[l]      = make_float2(vx, vx);
    ((float2*)pd[0])[l + 32] = make_float2(vy, vy);
    __syncwarp();

    float gx0 = ex2f(fmaf(emb[1 * NT + l], L2E, -6.0f));
    float gy0 = ex2f(fmaf(emb[1 * NT + l + 32], L2E, -6.0f));
    int   qm0 = (int)mrow[1];
    float gx1 = ex2f(fmaf(emb[2 * NT + l], L2E, -6.0f));
    float gy1 = ex2f(fmaf(emb[2 * NT + l + 32], L2E, -6.0f));
    int   qm1 = (int)mrow[2];
    float gx2 = ex2f(fmaf(emb[3 * NT + l], L2E, -6.0f));
    float gy2 = ex2f(fmaf(emb[3 * NT + l + 32], L2E, -6.0f));
    int   qm2 = (int)mrow[3];
    float gx3 = ex2f(fmaf(emb[4 * NT + l], L2E, -6.0f));
    float gy3 = ex2f(fmaf(emb[4 * NT + l + 32], L2E, -6.0f));
    int   qm3 = (int)mrow[4];

    for (int t = 1; t <= SEQ - 15; t += 8) {
        CRF_STEP(t + 0, gx0, gy0, qm0, 0, 1, false);
        CRF_STEP(t + 1, gx1, gy1, qm1, 1, 0, false);
        CRF_STEP(t + 2, gx2, gy2, qm2, 0, 1, false);
        CRF_STEP(t + 3, gx3, gy3, qm3, 1, 0, false);
        CRF_STEP(t + 4, gx0, gy0, qm0, 0, 1, false);
        CRF_STEP(t + 5, gx1, gy1, qm1, 1, 0, false);
        CRF_STEP(t + 6, gx2, gy2, qm2, 0, 1, false);
        CRF_STEP(t + 7, gx3, gy3, qm3, 1, 0, true);
    }
    CRF_STEP(SEQ - 7, gx0, gy0, qm0, 0, 1, false);
    CRF_STEP(SEQ - 6, gx1, gy1, qm1, 1, 0, false);
    CRF_STEP(SEQ - 5, gx2, gy2, qm2, 0, 1, false);
    CRF_STEP(SEQ - 4, gx3, gy3, qm3, 1, 0, false);
    CRF_STEP(SEQ - 3, gx0, gy0, qm0, 0, 1, false);
    CRF_STEP(SEQ - 2, gx1, gy1, qm1, 1, 0, false);
    CRF_STEP(SEQ - 1, gx2, gy2, qm2, 0, 1, false);

    float s = vx * g_expEnd[l] + vy * g_expEnd[l + 32];
#pragma unroll
    for (int off = 16; off > 0; off >>= 1)
        s += __shfl_xor_sync(0xffffffffu, s, off);
    if (l == 0) g_logz[b] = (lg2f(s) + (float)c) * LN2;
}

// ---------------- gold-path score: one warp per batch ----------------
__global__ void __launch_bounds__(256) crf_score_kernel(
    const float* __restrict__ em, const float* __restrict__ startt,
    const float* __restrict__ endt, const float* __restrict__ trans)
{
    const int warp = threadIdx.x >> 5;
    const int lane = threadIdx.x & 31;
    const int b = blockIdx.x * 8 + warp;
    if (b >= BATCH) return;
    const float* emb = em + (size_t)b * SEQ * NT;
    const unsigned char* mrow = g_maskb + (size_t)b * SEQ;
    const int* tg = g_tagsi + (size_t)b * SEQ;

    float acc = 0.f;
    int msum = 0;
    for (int s = lane; s < SEQ; s += 32) {
        const int tcur = tg[s];
        const int mk = (int)mrow[s];
        const float e = emb[s * NT + tcur];
        float contrib;
        if (s == 0) {
            contrib = e + startt[tcur];
        } else {
            const int tprev = tg[s - 1];
            contrib = mk ? (e + trans[tprev * NT + tcur]) : 0.f;
        }
        acc += contrib;
        msum += mk ? 1 : 0;
    }
#pragma unroll
    for (int off = 16; off > 0; off >>= 1) {
        acc  += __shfl_xor_sync(0xffffffffu, acc, off);
        msum += __shfl_xor_sync(0xffffffffu, msum, off);
    }
    if (lane == 0) {
        const int send = msum - 1;
        g_score[b] = acc + endt[tg[send]];
    }
}

// ---------------- final deterministic reduce ----------------
__global__ void crf_reduce_kernel(float* __restrict__ out) {
    __shared__ float sh[BATCH];
    const int i = threadIdx.x;
    sh[i] = g_logz[i] - g_score[i];
    __syncthreads();
#pragma unroll
    for (int off = BATCH / 2; off > 0; off >>= 1) {
        if (i < off) sh[i] += sh[i + off];
        __syncthreads();
    }
    if (i == 0) out[0] = sh[0];
}

// ---------------- launch: size-based dispatch + content sniff ----------------
extern "C" void kernel_launch(void* const* d_in, const int* in_sizes, int n_in,
                              void* d_out, int out_size) {
    // By element count: emissions = largest; transitions = 4096; start/end = 64;
    // tags & mask = 524288 each -> resolved by on-device content sniff + repack.
    int i_em = 0;
    for (int i = 1; i < n_in; ++i) if (in_sizes[i] > in_sizes[i_em]) i_em = i;

    int i_tr = -1, i_s1 = -1, i_s2 = -1, i_b1 = -1, i_b2 = -1;
    for (int i = 0; i < n_in; ++i) {
        if (i == i_em) continue;
        if (in_sizes[i] == NT * NT) { i_tr = i; }
        else if (in_sizes[i] == NT) { if (i_s1 < 0) i_s1 = i; else i_s2 = i; }
        else { if (i_b1 < 0) i_b1 = i; else i_b2 = i; }
    }

    const float* em     = (const float*)d_in[i_em];
    const float* trans  = (const float*)d_in[i_tr];
    const float* startt = (const float*)d_in[i_s1];
    const float* endt   = (const float*)d_in[i_s2];

    crf_sniff_kernel<<<1, 1>>>((const unsigned int*)d_in[i_b1],
                               (const unsigned int*)d_in[i_b2]);
    crf_repack_kernel<<<NSB / 256, 256>>>();
    crf_prep_kernel<<<(NT * NT + 255) / 256, 256>>>(trans, endt);
    crf_forward_kernel<<<BATCH, 32>>>(em, startt);
    crf_score_kernel<<<BATCH / 8, 256>>>(em, startt, endt, trans);
    crf_reduce_kernel<<<1, BATCH>>>((float*)d_out);
}

// round 6
// speedup vs baseline: 1.1674x; 1.1674x over previous
#include <cuda_runtime.h>
#include <cuda_bf16.h>
#include <cstdint>

#define BATCH 512
#define SEQ   1024
#define NT    64
#define NSB   (BATCH * SEQ)
#define FW_WARPS 4

// ---------------- device scratch (no allocs allowed) ----------------
__device__ float g_expT[NT * NT];   // exp(transitions)
__device__ float g_expEnd[NT];      // exp(end_transitions)
__device__ float g_logz[BATCH];
__device__ float g_score[BATCH];
__device__ unsigned long long g_mask_ptr;   // resolved raw mask pointer
__device__ unsigned long long g_tags_ptr;   // resolved raw tags pointer
__device__ int   g_mask8;                   // 1 if mask is 1 byte/elem, 0 if int32
__device__ int   g_tags64;                  // 1 if tags are int64, 0 if int32
__device__ unsigned char g_maskb[NSB];      // canonical mask (1 byte/elem)
__device__ int           g_tagsi[NSB];      // canonical tags (int32)

// ---------------- small PTX helpers ----------------
__device__ __forceinline__ float ex2f(float x) {
    float r; asm("ex2.approx.ftz.f32 %0, %1;" : "=f"(r) : "f"(x)); return r;
}
__device__ __forceinline__ float lg2f(float x) {
    float r; asm("lg2.approx.ftz.f32 %0, %1;" : "=f"(r) : "f"(x)); return r;
}
__device__ __forceinline__ unsigned long long pack2(float x, float y) {
    unsigned long long r; asm("mov.b64 %0, {%1, %2};" : "=l"(r) : "f"(x), "f"(y)); return r;
}
__device__ __forceinline__ void unpack2(unsigned long long v, float& x, float& y) {
    asm("mov.b64 {%0, %1}, %2;" : "=f"(x), "=f"(y) : "l"(v));
}
__device__ __forceinline__ unsigned long long ffma2(unsigned long long a, unsigned long long b, unsigned long long c) {
    unsigned long long d; asm("fma.rn.f32x2 %0, %1, %2, %3;" : "=l"(d) : "l"(a), "l"(b), "l"(c)); return d;
}
__device__ __forceinline__ unsigned long long fadd2(unsigned long long a, unsigned long long b) {
    unsigned long long d; asm("add.rn.f32x2 %0, %1, %2;" : "=l"(d) : "l"(a), "l"(b)); return d;
}

// ---------------- content + width sniff (one warp, parallel) ----------------
__global__ void __launch_bounds__(32) crf_sniff_kernel(const unsigned int* __restrict__ a,
                                                       const unsigned int* __restrict__ b) {
    const int l = threadIdx.x;
    const unsigned int a0 = a[l], a1 = a[l + 32];
    const unsigned int b0 = b[l], b1 = b[l + 32];
    // mask buffer: every byte 0/1
    const int am = __all_sync(0xffffffffu, ((a0 | a1) & 0xFEFEFEFEu) == 0u);
    const int bm = __all_sync(0xffffffffu, ((b0 | b1) & 0xFEFEFEFEu) == 0u);
    const unsigned int* mp = am ? a : b;
    const unsigned int* tp = am ? b : a;
    // mask width: byte-mask has a word with value > 1 (packed 0x01 bytes)
    const unsigned int m0 = mp[l], m1 = mp[l + 32];
    const int m8 = __any_sync(0xffffffffu, (m0 > 1u) || (m1 > 1u));
    // tags width: int64 <=> odd 32-bit words all zero
    const unsigned int todd = tp[2 * l + 1];
    const int t64 = __all_sync(0xffffffffu, todd == 0u);
    if (l == 0) {
        g_mask_ptr = (unsigned long long)mp;
        g_tags_ptr = (unsigned long long)tp;
        g_mask8 = m8;
        g_tags64 = t64;
    }
}

// ---------------- repack mask/tags into canonical layouts ----------------
__global__ void crf_repack_kernel() {
    const int i = blockIdx.x * blockDim.x + threadIdx.x;
    if (i >= NSB) return;
    if (g_mask8) {
        g_maskb[i] = (((const unsigned char*)g_mask_ptr)[i] != 0) ? 1 : 0;
    } else {
        g_maskb[i] = (((const unsigned int*)g_mask_ptr)[i] != 0u) ? 1 : 0;
    }
    if (g_tags64) {
        g_tagsi[i] = (int)((const long long*)g_tags_ptr)[i];
    } else {
        g_tagsi[i] = ((const int*)g_tags_ptr)[i];
    }
}

// ---------------- prep: E = exp(T), expEnd = exp(end) ----------------
__global__ void crf_prep_kernel(const float* __restrict__ trans, const float* __restrict__ endt) {
    int i = blockIdx.x * blockDim.x + threadIdx.x;
    if (i < NT * NT) g_expT[i] = expf(trans[i]);
    if (i < NT)      g_expEnd[i] = expf(endt[i]);
}

// ---------------- forward: 4 warps/CTA, one batch per warp ----------------
// Lane l owns adjacent outputs j0=2l, j1=2l+1.
// v stored as float2(v_{2l}, v_{2l+1}); read back as 16 broadcast LDS.128
// giving natural consecutive-i multiplier pairs (v_{2i}, v_{2i+1}).
// E regs: EA[p] = (E[2p][j0], E[2p+1][j0]),  EB[p] = (E[2p][j1], E[2p+1][j1]).
// Invariant: alpha[j] = ln(v[j]) + c*ln2.
// Step: out_j = sum_i v_i E_ij; v' = out * g, g = exp2(em*L2E - 6) (prefetched); c += 6.
// Every 8th step: absolute renorm by 2^(133-eb(out_{j=0})); c += eb - 127 (exact).
#define CRF_STEP(T, GX, GY, QM, RBUF, WBUF, REN) do {                            \
    const int   mcur = (QM);                                                     \
    const float gx_c = (GX), gy_c = (GY);                                        \
    { /* prefetch step T+4 */                                                    \
        const int tp = (T) + 4;                                                  \
        if (tp < SEQ) {                                                          \
            const float2 e2 = *(const float2*)(emb + tp * NT + 2 * l);           \
            GX = ex2f(fmaf(e2.x, L2E, -6.0f));                                   \
            GY = ex2f(fmaf(e2.y, L2E, -6.0f));                                   \
            QM = (int)mrow[tp];                                                  \
        }                                                                        \
    }                                                                            \
    const ulonglong2* pb = (const ulonglong2*)(pd[wid][RBUF]);                   \
    unsigned long long a0 = 0ull, a1 = 0ull, b0 = 0ull, b1 = 0ull;               \
    _Pragma("unroll")                                                            \
    for (int q = 0; q < 16; ++q) {                                               \
        const ulonglong2 qq = pb[q];                                             \
        a0 = ffma2(qq.x, EA[2 * q],     a0);                                     \
        a1 = ffma2(qq.y, EA[2 * q + 1], a1);                                     \
        b0 = ffma2(qq.x, EB[2 * q],     b0);                                     \
        b1 = ffma2(qq.y, EB[2 * q + 1], b1);                                     \
    }                                                                            \
    const unsigned long long ta = fadd2(a0, a1);                                 \
    const unsigned long long tb = fadd2(b0, b1);                                 \
    float ax, ay, bx, by;                                                        \
    unpack2(ta, ax, ay); unpack2(tb, bx, by);                                    \
    const float outA = ax + ay;                                                  \
    const float outB = bx + by;                                                  \
    if (REN) {                                                                   \
        const float arefn = __shfl_sync(0xffffffffu, outA, 0);                   \
        const int eb = (__float_as_int(arefn) >> 23) & 255;                      \
        if (mcur) {                                                              \
            const float s2 = __int_as_float((260 - eb) << 23);                   \
            vx = outA * gx_c * s2;                                               \
            vy = outB * gy_c * s2;                                               \
            c += eb - 127;                                                       \
        }                                                                        \
    } else if (mcur) {                                                           \
        vx = outA * gx_c;                                                        \
        vy = outB * gy_c;                                                        \
        c += 6;                                                                  \
    }                                                                            \
    ((float2*)pd[wid][WBUF])[l] = make_float2(vx, vy);                           \
    __syncwarp();                                                                \
} while (0)

__global__ void __launch_bounds__(32 * FW_WARPS, 1) crf_forward_kernel(
    const float* __restrict__ em, const float* __restrict__ startt)
{
    __shared__ __align__(16) float pd[FW_WARPS][2][NT];  // per-warp double buffer
    const int wid = threadIdx.x >> 5;
    const int l = threadIdx.x & 31;
    const int b = blockIdx.x * FW_WARPS + wid;
    const float L2E = 1.4426950408889634f;
    const float LN2 = 0.69314718055994531f;

    // register-resident E column pairs for outputs j0=2l, j1=2l+1
    unsigned long long EA[32], EB[32];
#pragma unroll
    for (int p = 0; p < 32; ++p) {
        EA[p] = pack2(g_expT[(2 * p) * NT + 2 * l],     g_expT[(2 * p + 1) * NT + 2 * l]);
        EB[p] = pack2(g_expT[(2 * p) * NT + 2 * l + 1], g_expT[(2 * p + 1) * NT + 2 * l + 1]);
    }

    const float* emb = em + (size_t)b * SEQ * NT;
    const unsigned char* mrow = g_maskb + (size_t)b * SEQ;

    // init: v0 = exp(start + em0)
    const float2 st2 = *(const float2*)(startt + 2 * l);
    const float2 e02 = *(const float2*)(emb + 2 * l);
    float vx = ex2f((st2.x + e02.x) * L2E);
    float vy = ex2f((st2.y + e02.y) * L2E);
    int c = 0;

    ((float2*)pd[wid][0])[l] = make_float2(vx, vy);
    __syncwarp();

    // prefetch slots for steps 1..4 (slot = (step-1) & 3)
    float gx0, gy0, gx1, gy1, gx2, gy2, gx3, gy3;
    int qm0, qm1, qm2, qm3;
    {
        const float2 p1 = *(const float2*)(emb + 1 * NT + 2 * l);
        gx0 = ex2f(fmaf(p1.x, L2E, -6.0f)); gy0 = ex2f(fmaf(p1.y, L2E, -6.0f)); qm0 = (int)mrow[1];
        const float2 p2 = *(const float2*)(emb + 2 * NT + 2 * l);
        gx1 = ex2f(fmaf(p2.x, L2E, -6.0f)); gy1 = ex2f(fmaf(p2.y, L2E, -6.0f)); qm1 = (int)mrow[2];
        const float2 p3 = *(const float2*)(emb + 3 * NT + 2 * l);
        gx2 = ex2f(fmaf(p3.x, L2E, -6.0f)); gy2 = ex2f(fmaf(p3.y, L2E, -6.0f)); qm2 = (int)mrow[3];
        const float2 p4 = *(const float2*)(emb + 4 * NT + 2 * l);
        gx3 = ex2f(fmaf(p4.x, L2E, -6.0f)); gy3 = ex2f(fmaf(p4.y, L2E, -6.0f)); qm3 = (int)mrow[4];
    }

    // main loop: steps 1..1016, unroll 8; renorm every 8th
    for (int t = 1; t <= SEQ - 15; t += 8) {
        CRF_STEP(t + 0, gx0, gy0, qm0, 0, 1, false);
        CRF_STEP(t + 1, gx1, gy1, qm1, 1, 0, false);
        CRF_STEP(t + 2, gx2, gy2, qm2, 0, 1, false);
        CRF_STEP(t + 3, gx3, gy3, qm3, 1, 0, false);
        CRF_STEP(t + 4, gx0, gy0, qm0, 0, 1, false);
        CRF_STEP(t + 5, gx1, gy1, qm1, 1, 0, false);
        CRF_STEP(t + 6, gx2, gy2, qm2, 0, 1, false);
        CRF_STEP(t + 7, gx3, gy3, qm3, 1, 0, true);
    }
    // tail: steps 1017..1023
    CRF_STEP(SEQ - 7, gx0, gy0, qm0, 0, 1, false);
    CRF_STEP(SEQ - 6, gx1, gy1, qm1, 1, 0, false);
    CRF_STEP(SEQ - 5, gx2, gy2, qm2, 0, 1, false);
    CRF_STEP(SEQ - 4, gx3, gy3, qm3, 1, 0, false);
    CRF_STEP(SEQ - 3, gx0, gy0, qm0, 0, 1, false);
    CRF_STEP(SEQ - 2, gx1, gy1, qm1, 1, 0, false);
    CRF_STEP(SEQ - 1, gx2, gy2, qm2, 0, 1, false);

    // finalize: log_z = ln(sum_j v_j * expEnd_j) + c*ln2
    float s = vx * g_expEnd[2 * l] + vy * g_expEnd[2 * l + 1];
#pragma unroll
    for (int off = 16; off > 0; off >>= 1)
        s += __shfl_xor_sync(0xffffffffu, s, off);
    if (l == 0) g_logz[b] = (lg2f(s) + (float)c) * LN2;
}

// ---------------- gold-path score: one warp per batch ----------------
__global__ void __launch_bounds__(256) crf_score_kernel(
    const float* __restrict__ em, const float* __restrict__ startt,
    const float* __restrict__ endt, const float* __restrict__ trans)
{
    const int warp = threadIdx.x >> 5;
    const int lane = threadIdx.x & 31;
    const int b = blockIdx.x * 8 + warp;
    if (b >= BATCH) return;
    const float* emb = em + (size_t)b * SEQ * NT;
    const unsigned char* mrow = g_maskb + (size_t)b * SEQ;
    const int* tg = g_tagsi + (size_t)b * SEQ;

    float acc = 0.f;
    int msum = 0;
    for (int s = lane; s < SEQ; s += 32) {
        const int tcur = tg[s];
        const int mk = (int)mrow[s];
        const float e = emb[s * NT + tcur];
        float contrib;
        if (s == 0) {
            contrib = e + startt[tcur];
        } else {
            const int tprev = tg[s - 1];
            contrib = mk ? (e + trans[tprev * NT + tcur]) : 0.f;
        }
        acc += contrib;
        msum += mk ? 1 : 0;
    }
#pragma unroll
    for (int off = 16; off > 0; off >>= 1) {
        acc  += __shfl_xor_sync(0xffffffffu, acc, off);
        msum += __shfl_xor_sync(0xffffffffu, msum, off);
    }
    if (lane == 0) {
        const int send = msum - 1;
        g_score[b] = acc + endt[tg[send]];
    }
}

// ---------------- final deterministic reduce ----------------
__global__ void crf_reduce_kernel(float* __restrict__ out) {
    __shared__ float sh[BATCH];
    const int i = threadIdx.x;
    sh[i] = g_logz[i] - g_score[i];
    __syncthreads();
#pragma unroll
    for (int off = BATCH / 2; off > 0; off >>= 1) {
        if (i < off) sh[i] += sh[i + off];
        __syncthreads();
    }
    if (i == 0) out[0] = sh[0];
}

// ---------------- launch: size-based dispatch + content sniff ----------------
extern "C" void kernel_launch(void* const* d_in, const int* in_sizes, int n_in,
                              void* d_out, int out_size) {
    int i_em = 0;
    for (int i = 1; i < n_in; ++i) if (in_sizes[i] > in_sizes[i_em]) i_em = i;

    int i_tr = -1, i_s1 = -1, i_s2 = -1, i_b1 = -1, i_b2 = -1;
    for (int i = 0; i < n_in; ++i) {
        if (i == i_em) continue;
        if (in_sizes[i] == NT * NT) { i_tr = i; }
        else if (in_sizes[i] == NT) { if (i_s1 < 0) i_s1 = i; else i_s2 = i; }
        else { if (i_b1 < 0) i_b1 = i; else i_b2 = i; }
    }

    const float* em     = (const float*)d_in[i_em];
    const float* trans  = (const float*)d_in[i_tr];
    const float* startt = (const float*)d_in[i_s1];
    const float* endt   = (const float*)d_in[i_s2];

    crf_sniff_kernel<<<1, 32>>>((const unsigned int*)d_in[i_b1],
                                (const unsigned int*)d_in[i_b2]);
    crf_repack_kernel<<<NSB / 256, 256>>>();
    crf_prep_kernel<<<(NT * NT + 255) / 256, 256>>>(trans, endt);
    crf_forward_kernel<<<BATCH / FW_WARPS, 32 * FW_WARPS>>>(em, startt);
    crf_score_kernel<<<BATCH / 8, 256>>>(em, startt, endt, trans);
    crf_reduce_kernel<<<1, BATCH>>>((float*)d_out);
}